// round 11
// baseline (speedup 1.0000x reference)
#include <cuda_runtime.h>
#include <cuda_bf16.h>
#include <math.h>
#include <cstdint>

#define B_ 2
#define L_ 256
#define H_ 256
#define C_ 5
#define VOCAB 255   // 2*127 + 1 distinct clipped distances

// ---- scratch (no cudaMalloc allowed) ----
__device__ __align__(16) float g_Rt[VOCAB * H_];            // table@Wh_w + Wh_b   [255,256]
__device__ __align__(16) float g_A [B_ * L_ * H_];          // hs @ (We + Wd)
__device__ __align__(16) __nv_bfloat16 g_hsb[B_ * L_ * H_]; // bf16 hidden_state
__device__ __align__(16) __nv_bfloat16 g_Wm [H_ * H_];      // bf16 Wm
__device__ __align__(16) __nv_bfloat16 g_Wb [H_ * H_];      // bf16 (Ws - Wd)

// ---------------------------------------------------------------------------
// prep: bf16 conversions
// ---------------------------------------------------------------------------
__global__ void prep_kernel(const float* __restrict__ hs,
                            const float* __restrict__ Wh_w) {
    int idx = blockIdx.x * 256 + threadIdx.x;
    if (idx < B_ * L_ * H_)
        g_hsb[idx] = __float2bfloat16(hs[idx]);
    int r = idx - B_ * L_ * H_;
    if (r >= 0 && r < H_ * H_)
        g_Wm[r] = __float2bfloat16(Wh_w[3 * H_ * H_ + r]);
    int r2 = r - H_ * H_;
    if (r2 >= 0 && r2 < H_ * H_)
        g_Wb[r2] = __float2bfloat16(Wh_w[1 * H_ * H_ + r2] - Wh_w[2 * H_ * H_ + r2]);
}

// ---------------------------------------------------------------------------
// relterm (fp32): Rt[d,h] = sum_k table[d,k]*Wh_w[k,h] + Wh_b[h]
// 5 distance rows per block (255 = 51*5): L2 traffic 51MB total.
// ---------------------------------------------------------------------------
__global__ void relterm_kernel(const float* __restrict__ Wh_w,
                               const float* __restrict__ Wh_b) {
    __shared__ float tbl[5][4 * H_];
    const int d0 = blockIdx.x * 5;
    const int h  = threadIdx.x;
    const float cst = -logf(10000.0f) / (float)(4 * H_);
    for (int k = h; k < 4 * H_; k += H_) {
        int kk = k & ~1;
        float w = expf(cst * (float)kk);
        #pragma unroll
        for (int r = 0; r < 5; r++) {
            float ang = (float)(d0 + r) * w;
            tbl[r][k] = (k & 1) ? cosf(ang) : sinf(ang);
        }
    }
    __syncthreads();
    float a[5];
    #pragma unroll
    for (int r = 0; r < 5; r++) a[r] = Wh_b[h];
    #pragma unroll 4
    for (int k = 0; k < 4 * H_; k++) {
        float wv = Wh_w[k * H_ + h];
        #pragma unroll
        for (int r = 0; r < 5; r++)
            a[r] = fmaf(tbl[r][k], wv, a[r]);
    }
    #pragma unroll
    for (int r = 0; r < 5; r++)
        g_Rt[(d0 + r) * H_ + h] = a[r];
}

// ---------------------------------------------------------------------------
// A[r,h] = hs[r,:] @ (We + Wd). 16 rows/block: L2 traffic 16MB total.
// ---------------------------------------------------------------------------
__global__ void a_kernel(const float* __restrict__ hs,
                         const float* __restrict__ Wh_w) {
    __shared__ float rows[16][H_];
    int rb = blockIdx.x * 16;
    int h  = threadIdx.x;
    #pragma unroll
    for (int r = 0; r < 16; r++)
        rows[r][h] = hs[(rb + r) * H_ + h];
    __syncthreads();
    float acc[16];
    #pragma unroll
    for (int r = 0; r < 16; r++) acc[r] = 0.f;
    #pragma unroll 2
    for (int k = 0; k < H_; k++) {
        float wa = Wh_w[k * H_ + h] + Wh_w[(2 * H_ + k) * H_ + h];
        #pragma unroll
        for (int r = 0; r < 16; r++)
            acc[r] = fmaf(rows[r][k], wa, acc[r]);
    }
    #pragma unroll
    for (int r = 0; r < 16; r++)
        g_A[(rb + r) * H_ + h] = acc[r];
}

// ---------------------------------------------------------------------------
// main: per block (b, i, j-tile of 128). bf16 mma.sync GEMM M=128 N=256 K=256.
// Both operands fully SMEM-resident (stride 264 bf16 = 528B rows, conflict-free
// for ldsm: row starts hit banks 4r mod 32). Stage once -> one sync -> pure
// barrier-free MMA loop -> fused tanh/Wo epilogue.
// ---------------------------------------------------------------------------
#define BM 128
#define SS 264
#define NT 512

// dynamic smem layout (bytes)
#define OFF_AS   0
#define OFF_BS   67584                 // 128*264*2
#define OFF_WO   202752                // +256*264*2
#define OFF_AI   210944                // +256*8*4
#define OFF_HIB  211968                // +256*4
#define OFF_WOB  212480                // +256*2
#define OFF_RED  212544                // +64
#define SMEM_TOTAL 215104              // +128*5*4

__device__ __forceinline__ float tanha(float x) {
    float r; asm("tanh.approx.f32 %0, %1;" : "=f"(r) : "f"(x)); return r;
}
__device__ __forceinline__ void ldsm4(unsigned r[4], uint32_t a) {
    asm volatile("ldmatrix.sync.aligned.m8n8.x4.shared.b16 {%0,%1,%2,%3}, [%4];"
                 : "=r"(r[0]), "=r"(r[1]), "=r"(r[2]), "=r"(r[3]) : "r"(a));
}
__device__ __forceinline__ void ldsm4t(unsigned r[4], uint32_t a) {
    asm volatile("ldmatrix.sync.aligned.m8n8.x4.trans.shared.b16 {%0,%1,%2,%3}, [%4];"
                 : "=r"(r[0]), "=r"(r[1]), "=r"(r[2]), "=r"(r[3]) : "r"(a));
}
__device__ __forceinline__ void mma16816(float d[4], const unsigned a[4], const unsigned b[2]) {
    asm volatile("mma.sync.aligned.m16n8k16.row.col.f32.bf16.bf16.f32 "
                 "{%0,%1,%2,%3}, {%4,%5,%6,%7}, {%8,%9}, {%0,%1,%2,%3};"
                 : "+f"(d[0]), "+f"(d[1]), "+f"(d[2]), "+f"(d[3])
                 : "r"(a[0]), "r"(a[1]), "r"(a[2]), "r"(a[3]), "r"(b[0]), "r"(b[1]));
}

__global__ __launch_bounds__(NT, 1)
void main_kernel(const int*   __restrict__ mask,
                 const float* __restrict__ Wo_w,
                 const float* __restrict__ Wo_b,
                 float* __restrict__ out) {
    extern __shared__ __align__(16) char dynS[];
    __nv_bfloat16* As   = (__nv_bfloat16*)(dynS + OFF_AS);
    __nv_bfloat16* Bs   = (__nv_bfloat16*)(dynS + OFF_BS);
    float*         woS  = (float*)        (dynS + OFF_WO);
    float*         aiS  = (float*)        (dynS + OFF_AI);
    __nv_bfloat16* hibS = (__nv_bfloat16*)(dynS + OFF_HIB);
    float*         wobS = (float*)        (dynS + OFF_WOB);
    float*         red  = (float*)        (dynS + OFF_RED);

    const int jt = blockIdx.x, i = blockIdx.y, b = blockIdx.z;
    const int jbase = jt * BM;
    const int tid  = threadIdx.x;
    const int lane = tid & 31, warp = tid >> 5;
    const int wm = warp >> 2, wn = warp & 3;   // warp tile: m = wm*32, n = wn*64

    // ---- preload small tensors ----
    if (tid < H_) {
        hibS[tid] = g_hsb[(b * L_ + i) * H_ + tid];
        aiS[tid]  = g_A[(b * L_ + i) * H_ + tid];
    }
    for (int t = tid; t < H_ * C_; t += NT)
        woS[(t / C_) * 8 + (t % C_)] = Wo_w[t];
    if (tid < C_) wobS[tid] = Wo_b[tid];
    for (int t = tid; t < BM * C_; t += NT) red[t] = 0.f;
    __syncthreads();   // hibS must be visible to Bs staging

    // ---- stage As (pure copy): lane-per-row mapping, conflict-free ----
    {
        const int sj = tid & 127;
        const int sk = (tid >> 7) * 8;
        const __nv_bfloat16* hsrow = g_hsb + (b * L_ + jbase + sj) * H_;
        #pragma unroll
        for (int kc = 0; kc < H_; kc += 32)
            *(uint4*)&As[sj * SS + kc + sk] = *(const uint4*)&hsrow[kc + sk];
    }
    // ---- stage Bs[k][h] = hi[k]*Wm[k,h] + Wb[k,h]: warp-per-row ----
    {
        #pragma unroll
        for (int pass = 0; pass < 16; pass++) {
            int kr = pass * 16 + warp;
            __nv_bfloat162 h2 = __bfloat162bfloat162(hibS[kr]);
            const __nv_bfloat162* wmp = (const __nv_bfloat162*)&g_Wm[kr * H_ + lane * 8];
            const __nv_bfloat162* wbp = (const __nv_bfloat162*)&g_Wb[kr * H_ + lane * 8];
            __nv_bfloat162 t4[4];
            #pragma unroll
            for (int q = 0; q < 4; q++)
                t4[q] = __hfma2(h2, wmp[q], wbp[q]);
            *(uint4*)&Bs[kr * SS + lane * 8] = *(uint4*)t4;
        }
    }
    __syncthreads();   // the only barrier before the MMA loop

    float acc[2][8][4];
    #pragma unroll
    for (int mt = 0; mt < 2; mt++)
        #pragma unroll
        for (int nt = 0; nt < 8; nt++)
            #pragma unroll
            for (int q = 0; q < 4; q++) acc[mt][nt][q] = 0.f;

    const uint32_t AsA = (uint32_t)__cvta_generic_to_shared(As);
    const uint32_t BsA = (uint32_t)__cvta_generic_to_shared(Bs);
    const int g  = lane >> 3, r8 = lane & 7;
    const int arow  = ((g & 1) << 3) + r8;
    const int acolg = (g >> 1) << 3;
    const int browg = ((g & 1) << 3) + r8;
    const int bcol  = (g >> 1) << 3;

    // ---- barrier-free MMA loop over K=256 ----
    #pragma unroll 2
    for (int ks = 0; ks < H_; ks += 16) {
        unsigned af[2][4], bfr[8][2];
        #pragma unroll
        for (int mt = 0; mt < 2; mt++)
            ldsm4(af[mt], AsA + (((wm * 32 + mt * 16 + arow) * SS + ks + acolg) << 1));
        #pragma unroll
        for (int p = 0; p < 4; p++) {
            unsigned q[4];
            ldsm4t(q, BsA + (((ks + browg) * SS + wn * 64 + p * 16 + bcol) << 1));
            bfr[2 * p][0] = q[0]; bfr[2 * p][1] = q[1];
            bfr[2 * p + 1][0] = q[2]; bfr[2 * p + 1][1] = q[3];
        }
        #pragma unroll
        for (int mt = 0; mt < 2; mt++)
            #pragma unroll
            for (int nt = 0; nt < 8; nt++)
                mma16816(acc[mt][nt], af[mt], bfr[nt]);
    }

    // ---- fused epilogue ----
    float ps[4][C_];
    #pragma unroll
    for (int ri = 0; ri < 4; ri++)
        #pragma unroll
        for (int cc = 0; cc < C_; cc++) ps[ri][cc] = 0.f;

    const int rb = lane >> 2, qc = (lane & 3) * 2;
    #pragma unroll
    for (int nt = 0; nt < 8; nt++) {
        int c = wn * 64 + nt * 8 + qc;
        float ai0 = aiS[c], ai1 = aiS[c + 1];
        float4 wv0 = *(const float4*)&woS[c * 8];
        float  w04 = woS[c * 8 + 4];
        float4 wv1 = *(const float4*)&woS[(c + 1) * 8];
        float  w14 = woS[(c + 1) * 8 + 4];
        float w0[5] = {wv0.x, wv0.y, wv0.z, wv0.w, w04};
        float w1[5] = {wv1.x, wv1.y, wv1.z, wv1.w, w14};
        #pragma unroll
        for (int mt = 0; mt < 2; mt++) {
            int r0 = wm * 32 + mt * 16 + rb;
            int r1 = r0 + 8;
            int j0 = jbase + r0, j1 = jbase + r1;
            int d0 = min(max(j0 - i, -127), 127) + 127;
            int d1 = min(max(j1 - i, -127), 127) + 127;
            float2 R0 = *(const float2*)&g_Rt[d0 * H_ + c];
            float2 R1 = *(const float2*)&g_Rt[d1 * H_ + c];
            const float* a4 = acc[mt][nt];
            float t00 = tanha(a4[0] + ai0 + R0.x);
            float t01 = tanha(a4[1] + ai1 + R0.y);
            float t10 = tanha(a4[2] + ai0 + R1.x);
            float t11 = tanha(a4[3] + ai1 + R1.y);
            #pragma unroll
            for (int cc = 0; cc < C_; cc++) {
                ps[2 * mt][cc]     = fmaf(t00, w0[cc], fmaf(t01, w1[cc], ps[2 * mt][cc]));
                ps[2 * mt + 1][cc] = fmaf(t10, w0[cc], fmaf(t11, w1[cc], ps[2 * mt + 1][cc]));
            }
        }
    }

    // quad-reduce (cols within quad are disjoint) then smem atomic across n-warps
    #pragma unroll
    for (int ri = 0; ri < 4; ri++) {
        int row = wm * 32 + (ri >> 1) * 16 + (ri & 1) * 8 + rb;
        #pragma unroll
        for (int cc = 0; cc < C_; cc++) {
            float v = ps[ri][cc];
            v += __shfl_xor_sync(0xffffffffu, v, 1);
            v += __shfl_xor_sync(0xffffffffu, v, 2);
            if ((lane & 3) == 0) atomicAdd(&red[row * C_ + cc], v);
        }
    }
    __syncthreads();

    if (tid < BM) {
        int j  = jbase + tid;
        int mi = mask[b * L_ + i];
        int mj = mask[b * L_ + j];
        bool bad = (!mi) || (!mj);
        #pragma unroll
        for (int cc = 0; cc < C_; cc++) {
            float v = red[tid * C_ + cc] + wobS[cc];
            if (bad) v = -INFINITY;
            if (i > j) v -= 1e12f;
            out[((b * C_ + cc) * L_ + i) * L_ + j] = v;
        }
    }
}

// ---------------------------------------------------------------------------
extern "C" void kernel_launch(void* const* d_in, const int* in_sizes, int n_in,
                              void* d_out, int out_size) {
    const float* hs   = (const float*)d_in[0];
    const int*   mask = (const int*)  d_in[1];
    const float* Wh_w = (const float*)d_in[2];
    const float* Wh_b = (const float*)d_in[3];
    const float* Wo_w = (const float*)d_in[4];
    const float* Wo_b = (const float*)d_in[5];
    float* out = (float*)d_out;

    cudaFuncSetAttribute(main_kernel,
                         cudaFuncAttributeMaxDynamicSharedMemorySize, SMEM_TOTAL);

    prep_kernel<<<(B_ * L_ * H_ + 2 * H_ * H_) / 256, 256>>>(hs, Wh_w);
    relterm_kernel<<<51, H_>>>(Wh_w, Wh_b);
    a_kernel<<<(B_ * L_) / 16, H_>>>(hs, Wh_w);
    dim3 grid(L_ / BM, L_, B_);
    main_kernel<<<grid, NT, SMEM_TOTAL>>>(mask, Wo_w, Wo_b, out);
}

// round 14
// speedup vs baseline: 1.1725x; 1.1725x over previous
#include <cuda_runtime.h>
#include <cuda_bf16.h>
#include <math.h>
#include <cstdint>

#define B_ 2
#define L_ 256
#define H_ 256
#define C_ 5
#define VOCAB 255   // 2*127 + 1 distinct clipped distances

// ---- scratch (no cudaMalloc allowed) ----
__device__ __align__(16) float g_Rt[VOCAB * H_];            // bias-init + split-K accum
__device__ __align__(16) float g_A [B_ * L_ * H_];          // hs @ (We + Wd)
__device__ __align__(16) __nv_bfloat16 g_hsb[B_ * L_ * H_]; // bf16 hidden_state
__device__ __align__(16) __nv_bfloat16 g_Wm [H_ * H_];      // bf16 Wm
__device__ __align__(16) __nv_bfloat16 g_Wb [H_ * H_];      // bf16 (Ws - Wd)

// ---------------------------------------------------------------------------
// prep: bf16 conversions + g_Rt := bias (for split-K relterm accumulation)
// ---------------------------------------------------------------------------
__global__ void prep_kernel(const float* __restrict__ hs,
                            const float* __restrict__ Wh_w,
                            const float* __restrict__ Wh_b) {
    int idx = blockIdx.x * 256 + threadIdx.x;
    if (idx < B_ * L_ * H_) {
        g_hsb[idx] = __float2bfloat16(hs[idx]);
        return;
    }
    int r = idx - B_ * L_ * H_;
    if (r < H_ * H_) {
        g_Wm[r] = __float2bfloat16(Wh_w[3 * H_ * H_ + r]);
        g_Wb[r] = __float2bfloat16(Wh_w[1 * H_ * H_ + r] - Wh_w[2 * H_ * H_ + r]);
        return;
    }
    int r2 = r - H_ * H_;
    if (r2 < VOCAB * H_)
        g_Rt[r2] = Wh_b[r2 & 255];
}

// ---------------------------------------------------------------------------
// relterm split-K: grid (51 d-groups, 4 k-quarters); atomicAdd into g_Rt.
// ---------------------------------------------------------------------------
__global__ void relterm_kernel(const float* __restrict__ Wh_w) {
    __shared__ float tbl[5][H_];
    const int d0 = blockIdx.x * 5;
    const int kq = blockIdx.y;
    const int h  = threadIdx.x;
    const float cst = -logf(10000.0f) / (float)(4 * H_);
    {
        int kg = kq * 256 + h;
        int kk = kg & ~1;
        float w = expf(cst * (float)kk);
        #pragma unroll
        for (int r = 0; r < 5; r++) {
            float ang = (float)(d0 + r) * w;
            tbl[r][h] = (kg & 1) ? cosf(ang) : sinf(ang);
        }
    }
    __syncthreads();
    float a[5] = {0.f, 0.f, 0.f, 0.f, 0.f};
    #pragma unroll 4
    for (int k = 0; k < 256; k++) {
        float wv = Wh_w[(kq * 256 + k) * H_ + h];
        #pragma unroll
        for (int r = 0; r < 5; r++)
            a[r] = fmaf(tbl[r][k], wv, a[r]);
    }
    #pragma unroll
    for (int r = 0; r < 5; r++)
        atomicAdd(&g_Rt[(d0 + r) * H_ + h], a[r]);
}

// ---------------------------------------------------------------------------
// A[r,h] = hs[r,:] @ (We + Wd). 16 rows/block.
// ---------------------------------------------------------------------------
__global__ void a_kernel(const float* __restrict__ hs,
                         const float* __restrict__ Wh_w) {
    __shared__ float rows[16][H_];
    int rb = blockIdx.x * 16;
    int h  = threadIdx.x;
    #pragma unroll
    for (int r = 0; r < 16; r++)
        rows[r][h] = hs[(rb + r) * H_ + h];
    __syncthreads();
    float acc[16];
    #pragma unroll
    for (int r = 0; r < 16; r++) acc[r] = 0.f;
    #pragma unroll 2
    for (int k = 0; k < H_; k++) {
        float wa = Wh_w[k * H_ + h] + Wh_w[(2 * H_ + k) * H_ + h];
        #pragma unroll
        for (int r = 0; r < 16; r++)
            acc[r] = fmaf(rows[r][k], wa, acc[r]);
    }
    #pragma unroll
    for (int r = 0; r < 16; r++)
        g_A[(rb + r) * H_ + h] = acc[r];
}

// ---------------------------------------------------------------------------
// main: per block (jt, i, b). bf16 mma.sync GEMM M=128 N=256 K=256.
// 1024 threads / 32 warps, warp tile 32x32 (4 m-groups x 8 n-groups) ->
// 32 fp32 accs/thread -> <=64 regs -> occ 50% (32 warps/SM).
// Both operands SMEM-resident; one barrier; fused tanh/Wo epilogue.
// ---------------------------------------------------------------------------
#define BM 128
#define SS 264
#define NT 1024

// dynamic smem layout (bytes)
#define OFF_AS   0
#define OFF_BS   67584                 // 128*264*2
#define OFF_WO   202752                // +256*264*2
#define OFF_AI   210944                // +256*8*4
#define OFF_HIB  211968                // +256*4
#define OFF_WOB  212480                // +256*2
#define OFF_RED  212544                // +64
#define SMEM_TOTAL 215104              // +128*5*4

__device__ __forceinline__ float tanha(float x) {
    float r; asm("tanh.approx.f32 %0, %1;" : "=f"(r) : "f"(x)); return r;
}
__device__ __forceinline__ void ldsm4(unsigned r[4], uint32_t a) {
    asm volatile("ldmatrix.sync.aligned.m8n8.x4.shared.b16 {%0,%1,%2,%3}, [%4];"
                 : "=r"(r[0]), "=r"(r[1]), "=r"(r[2]), "=r"(r[3]) : "r"(a));
}
__device__ __forceinline__ void ldsm4t(unsigned r[4], uint32_t a) {
    asm volatile("ldmatrix.sync.aligned.m8n8.x4.trans.shared.b16 {%0,%1,%2,%3}, [%4];"
                 : "=r"(r[0]), "=r"(r[1]), "=r"(r[2]), "=r"(r[3]) : "r"(a));
}
__device__ __forceinline__ void mma16816(float d[4], const unsigned a[4], const unsigned b[2]) {
    asm volatile("mma.sync.aligned.m16n8k16.row.col.f32.bf16.bf16.f32 "
                 "{%0,%1,%2,%3}, {%4,%5,%6,%7}, {%8,%9}, {%0,%1,%2,%3};"
                 : "+f"(d[0]), "+f"(d[1]), "+f"(d[2]), "+f"(d[3])
                 : "r"(a[0]), "r"(a[1]), "r"(a[2]), "r"(a[3]), "r"(b[0]), "r"(b[1]));
}

__global__ __launch_bounds__(NT, 1)
void main_kernel(const int*   __restrict__ mask,
                 const float* __restrict__ Wo_w,
                 const float* __restrict__ Wo_b,
                 float* __restrict__ out) {
    extern __shared__ __align__(16) char dynS[];
    __nv_bfloat16* As   = (__nv_bfloat16*)(dynS + OFF_AS);
    __nv_bfloat16* Bs   = (__nv_bfloat16*)(dynS + OFF_BS);
    float*         woS  = (float*)        (dynS + OFF_WO);
    float*         aiS  = (float*)        (dynS + OFF_AI);
    __nv_bfloat16* hibS = (__nv_bfloat16*)(dynS + OFF_HIB);
    float*         wobS = (float*)        (dynS + OFF_WOB);
    float*         red  = (float*)        (dynS + OFF_RED);

    const int jt = blockIdx.x, i = blockIdx.y, b = blockIdx.z;
    const int jbase = jt * BM;
    const int tid  = threadIdx.x;
    const int lane = tid & 31, warp = tid >> 5;
    const int wm = warp & 3, wn = warp >> 2;   // warp tile: m = wm*32, n = wn*32

    // ---- preload small tensors ----
    if (tid < H_) {
        hibS[tid] = g_hsb[(b * L_ + i) * H_ + tid];
        aiS[tid]  = g_A[(b * L_ + i) * H_ + tid];
    }
    for (int t = tid; t < H_ * C_; t += NT)
        woS[(t / C_) * 8 + (t % C_)] = Wo_w[t];
    if (tid < C_) wobS[tid] = Wo_b[tid];
    for (int t = tid; t < BM * C_; t += NT) red[t] = 0.f;
    __syncthreads();   // hibS visible to Bs staging

    // ---- stage As (pure copy): 8 threads per row, conflict-free ----
    {
        const int sj = tid & 127;
        const int sk = (tid >> 7) * 8;     // 0..56
        const __nv_bfloat16* hsrow = g_hsb + (b * L_ + jbase + sj) * H_;
        #pragma unroll
        for (int kc = 0; kc < H_; kc += 64)
            *(uint4*)&As[sj * SS + kc + sk] = *(const uint4*)&hsrow[kc + sk];
    }
    // ---- stage Bs[k][h] = hi[k]*Wm[k,h] + Wb[k,h]: warp-per-row, 8 passes ----
    {
        #pragma unroll
        for (int pass = 0; pass < 8; pass++) {
            int kr = pass * 32 + warp;
            __nv_bfloat162 h2 = __bfloat162bfloat162(hibS[kr]);
            const __nv_bfloat162* wmp = (const __nv_bfloat162*)&g_Wm[kr * H_ + lane * 8];
            const __nv_bfloat162* wbp = (const __nv_bfloat162*)&g_Wb[kr * H_ + lane * 8];
            __nv_bfloat162 t4[4];
            #pragma unroll
            for (int q = 0; q < 4; q++)
                t4[q] = __hfma2(h2, wmp[q], wbp[q]);
            *(uint4*)&Bs[kr * SS + lane * 8] = *(uint4*)t4;
        }
    }
    __syncthreads();   // the only barrier before the MMA loop

    float acc[2][4][4];
    #pragma unroll
    for (int mt = 0; mt < 2; mt++)
        #pragma unroll
        for (int nt = 0; nt < 4; nt++)
            #pragma unroll
            for (int q = 0; q < 4; q++) acc[mt][nt][q] = 0.f;

    const uint32_t AsA = (uint32_t)__cvta_generic_to_shared(As);
    const uint32_t BsA = (uint32_t)__cvta_generic_to_shared(Bs);
    const int g  = lane >> 3, r8 = lane & 7;
    const int arow  = ((g & 1) << 3) + r8;
    const int acolg = (g >> 1) << 3;
    const int browg = ((g & 1) << 3) + r8;
    const int bcol  = (g >> 1) << 3;

    // ---- barrier-free MMA loop over K=256 ----
    #pragma unroll 2
    for (int ks = 0; ks < H_; ks += 16) {
        unsigned af[2][4], bfr[4][2];
        #pragma unroll
        for (int mt = 0; mt < 2; mt++)
            ldsm4(af[mt], AsA + (((wm * 32 + mt * 16 + arow) * SS + ks + acolg) << 1));
        #pragma unroll
        for (int p = 0; p < 2; p++) {
            unsigned q[4];
            ldsm4t(q, BsA + (((ks + browg) * SS + wn * 32 + p * 16 + bcol) << 1));
            bfr[2 * p][0] = q[0]; bfr[2 * p][1] = q[1];
            bfr[2 * p + 1][0] = q[2]; bfr[2 * p + 1][1] = q[3];
        }
        #pragma unroll
        for (int mt = 0; mt < 2; mt++)
            #pragma unroll
            for (int nt = 0; nt < 4; nt++)
                mma16816(acc[mt][nt], af[mt], bfr[nt]);
    }

    // ---- fused epilogue ----
    float ps[4][C_];
    #pragma unroll
    for (int ri = 0; ri < 4; ri++)
        #pragma unroll
        for (int cc = 0; cc < C_; cc++) ps[ri][cc] = 0.f;

    const int rb = lane >> 2, qc = (lane & 3) * 2;
    #pragma unroll
    for (int nt = 0; nt < 4; nt++) {
        int c = wn * 32 + nt * 8 + qc;
        float ai0 = aiS[c], ai1 = aiS[c + 1];
        float4 wv0 = *(const float4*)&woS[c * 8];
        float  w04 = woS[c * 8 + 4];
        float4 wv1 = *(const float4*)&woS[(c + 1) * 8];
        float  w14 = woS[(c + 1) * 8 + 4];
        float w0[5] = {wv0.x, wv0.y, wv0.z, wv0.w, w04};
        float w1[5] = {wv1.x, wv1.y, wv1.z, wv1.w, w14};
        #pragma unroll
        for (int mt = 0; mt < 2; mt++) {
            int r0 = wm * 32 + mt * 16 + rb;
            int r1 = r0 + 8;
            int j0 = jbase + r0, j1 = jbase + r1;
            int d0 = min(max(j0 - i, -127), 127) + 127;
            int d1 = min(max(j1 - i, -127), 127) + 127;
            float2 R0 = *(const float2*)&g_Rt[d0 * H_ + c];
            float2 R1 = *(const float2*)&g_Rt[d1 * H_ + c];
            const float* a4 = acc[mt][nt];
            float t00 = tanha(a4[0] + ai0 + R0.x);
            float t01 = tanha(a4[1] + ai1 + R0.y);
            float t10 = tanha(a4[2] + ai0 + R1.x);
            float t11 = tanha(a4[3] + ai1 + R1.y);
            #pragma unroll
            for (int cc = 0; cc < C_; cc++) {
                ps[2 * mt][cc]     = fmaf(t00, w0[cc], fmaf(t01, w1[cc], ps[2 * mt][cc]));
                ps[2 * mt + 1][cc] = fmaf(t10, w0[cc], fmaf(t11, w1[cc], ps[2 * mt + 1][cc]));
            }
        }
    }

    // quad-reduce (cols within quad are disjoint) then smem atomic across n-warps
    #pragma unroll
    for (int ri = 0; ri < 4; ri++) {
        int row = wm * 32 + (ri >> 1) * 16 + (ri & 1) * 8 + rb;
        #pragma unroll
        for (int cc = 0; cc < C_; cc++) {
            float v = ps[ri][cc];
            v += __shfl_xor_sync(0xffffffffu, v, 1);
            v += __shfl_xor_sync(0xffffffffu, v, 2);
            if ((lane & 3) == 0) atomicAdd(&red[row * C_ + cc], v);
        }
    }
    __syncthreads();

    if (tid < BM) {
        int j  = jbase + tid;
        int mi = mask[b * L_ + i];
        int mj = mask[b * L_ + j];
        bool bad = (!mi) || (!mj);
        #pragma unroll
        for (int cc = 0; cc < C_; cc++) {
            float v = red[tid * C_ + cc] + wobS[cc];
            if (bad) v = -INFINITY;
            if (i > j) v -= 1e12f;
            out[((b * C_ + cc) * L_ + i) * L_ + j] = v;
        }
    }
}

// ---------------------------------------------------------------------------
extern "C" void kernel_launch(void* const* d_in, const int* in_sizes, int n_in,
                              void* d_out, int out_size) {
    const float* hs   = (const float*)d_in[0];
    const int*   mask = (const int*)  d_in[1];
    const float* Wh_w = (const float*)d_in[2];
    const float* Wh_b = (const float*)d_in[3];
    const float* Wo_w = (const float*)d_in[4];
    const float* Wo_b = (const float*)d_in[5];
    float* out = (float*)d_out;

    cudaFuncSetAttribute(main_kernel,
                         cudaFuncAttributeMaxDynamicSharedMemorySize, SMEM_TOTAL);

    int prep_elems = B_ * L_ * H_ + H_ * H_ + VOCAB * H_;
    prep_kernel<<<(prep_elems + 255) / 256, 256>>>(hs, Wh_w, Wh_b);
    dim3 rg(51, 4);
    relterm_kernel<<<rg, H_>>>(Wh_w);
    a_kernel<<<(B_ * L_) / 16, H_>>>(hs, Wh_w);
    dim3 grid(L_ / BM, L_, B_);
    main_kernel<<<grid, NT, SMEM_TOTAL>>>(mask, Wo_w, Wo_b, out);
}

// round 15
// speedup vs baseline: 1.3257x; 1.1307x over previous
#include <cuda_runtime.h>
#include <cuda_bf16.h>
#include <math.h>
#include <cstdint>

#define B_ 2
#define L_ 256
#define H_ 256
#define C_ 5
#define VOCAB 255   // 2*127 + 1 distinct clipped distances

// ---- scratch (no cudaMalloc allowed) ----
__device__ __align__(16) float g_Rt[VOCAB * H_];            // bias-init + split-K accum
__device__ __align__(16) float g_A [B_ * L_ * H_];          // hs @ (We + Wd)
__device__ __align__(16) __nv_bfloat16 g_hsb[B_ * L_ * H_]; // bf16 hidden_state
__device__ __align__(16) __nv_bfloat16 g_Wm [H_ * H_];      // bf16 Wm
__device__ __align__(16) __nv_bfloat16 g_Wb [H_ * H_];      // bf16 (Ws - Wd)

// ---------------------------------------------------------------------------
// prep: bf16 conversions + g_Rt := bias (re-init every launch for split-K)
// ---------------------------------------------------------------------------
__global__ void prep_kernel(const float* __restrict__ hs,
                            const float* __restrict__ Wh_w,
                            const float* __restrict__ Wh_b) {
    int idx = blockIdx.x * 256 + threadIdx.x;
    if (idx < B_ * L_ * H_) {
        g_hsb[idx] = __float2bfloat16(hs[idx]);
        return;
    }
    int r = idx - B_ * L_ * H_;
    if (r < H_ * H_) {
        g_Wm[r] = __float2bfloat16(Wh_w[3 * H_ * H_ + r]);
        g_Wb[r] = __float2bfloat16(Wh_w[1 * H_ * H_ + r] - Wh_w[2 * H_ * H_ + r]);
        return;
    }
    int r2 = r - H_ * H_;
    if (r2 < VOCAB * H_)
        g_Rt[r2] = Wh_b[r2 & 255];
}

// ---------------------------------------------------------------------------
// relterm split-K: grid (51 d-groups, 4 k-quarters); atomicAdd into g_Rt.
// ---------------------------------------------------------------------------
__global__ void relterm_kernel(const float* __restrict__ Wh_w) {
    __shared__ float tbl[5][H_];
    const int d0 = blockIdx.x * 5;
    const int kq = blockIdx.y;
    const int h  = threadIdx.x;
    const float cst = -logf(10000.0f) / (float)(4 * H_);
    {
        int kg = kq * 256 + h;
        int kk = kg & ~1;
        float w = expf(cst * (float)kk);
        #pragma unroll
        for (int r = 0; r < 5; r++) {
            float ang = (float)(d0 + r) * w;
            tbl[r][h] = (kg & 1) ? cosf(ang) : sinf(ang);
        }
    }
    __syncthreads();
    float a[5] = {0.f, 0.f, 0.f, 0.f, 0.f};
    #pragma unroll 4
    for (int k = 0; k < 256; k++) {
        float wv = Wh_w[(kq * 256 + k) * H_ + h];
        #pragma unroll
        for (int r = 0; r < 5; r++)
            a[r] = fmaf(tbl[r][k], wv, a[r]);
    }
    #pragma unroll
    for (int r = 0; r < 5; r++)
        atomicAdd(&g_Rt[(d0 + r) * H_ + h], a[r]);
}

// ---------------------------------------------------------------------------
// A[r,h] = hs[r,:] @ (We + Wd). 16 rows/block.
// ---------------------------------------------------------------------------
__global__ void a_kernel(const float* __restrict__ hs,
                         const float* __restrict__ Wh_w) {
    __shared__ float rows[16][H_];
    int rb = blockIdx.x * 16;
    int h  = threadIdx.x;
    #pragma unroll
    for (int r = 0; r < 16; r++)
        rows[r][h] = hs[(rb + r) * H_ + h];
    __syncthreads();
    float acc[16];
    #pragma unroll
    for (int r = 0; r < 16; r++) acc[r] = 0.f;
    #pragma unroll 2
    for (int k = 0; k < H_; k++) {
        float wa = Wh_w[k * H_ + h] + Wh_w[(2 * H_ + k) * H_ + h];
        #pragma unroll
        for (int r = 0; r < 16; r++)
            acc[r] = fmaf(rows[r][k], wa, acc[r]);
    }
    #pragma unroll
    for (int r = 0; r < 16; r++)
        g_A[(rb + r) * H_ + h] = acc[r];
}

// ---------------------------------------------------------------------------
// out init: Wo_b - 1e12*tril - inf*mask. Mains atomicAdd pure partials on top.
// ---------------------------------------------------------------------------
__global__ void outinit_kernel(const int* __restrict__ mask,
                               const float* __restrict__ Wo_b,
                               float* __restrict__ out) {
    int idx = blockIdx.x * 256 + threadIdx.x;
    if (idx >= B_ * C_ * L_ * L_) return;
    int j = idx & 255;
    int i = (idx >> 8) & 255;
    int c = (idx >> 16) % C_;
    int b = idx / (C_ * L_ * L_);
    float v = Wo_b[c];
    if (i > j) v -= 1e12f;
    if (!mask[b * L_ + i] || !mask[b * L_ + j]) v = -INFINITY;
    out[idx] = v;
}

// ---------------------------------------------------------------------------
// main: per block (jt, ht, i, b). bf16 mma.sync GEMM M=128 N=128 K=256,
// BK=64 k-tiled smem (51KB) + <=64 regs -> 2 blocks/SM so epilogue/staging
// of one block overlaps the MMA loop of the co-resident block.
//   pre[j,h] = sum_k hsb[j,k]*(hi[k]*Wm[k,h]+Wb[k,h]) + A_i[h] + Rt[d,h]
//   partial  = tanh(pre) @ Wo_half  -> atomicAdd into pre-initialized out
// ---------------------------------------------------------------------------
#define BK  64
#define SAs 72     // As stride (bf16): 144B rows -> row starts 4 banks apart
#define SBs 136    // Bs stride (bf16): 272B rows -> same conflict-free pattern
#define NT  512

// dynamic smem layout (bytes)
#define OFF_AS   0                     // 128*72*2  = 18432
#define OFF_BS   18432                 // 64*136*2  = 17408
#define OFF_WO   35840                 // 128*8*4   = 4096
#define OFF_AI   39936                 // 128*4     = 512
#define OFF_HIB  40448                 // 256*2     = 512
#define OFF_RED  40960                 // 4*128*5*4 = 10240
#define SMEM_TOTAL 51200

__device__ __forceinline__ float tanha(float x) {
    float r; asm("tanh.approx.f32 %0, %1;" : "=f"(r) : "f"(x)); return r;
}
__device__ __forceinline__ void ldsm4(unsigned r[4], uint32_t a) {
    asm volatile("ldmatrix.sync.aligned.m8n8.x4.shared.b16 {%0,%1,%2,%3}, [%4];"
                 : "=r"(r[0]), "=r"(r[1]), "=r"(r[2]), "=r"(r[3]) : "r"(a));
}
__device__ __forceinline__ void ldsm4t(unsigned r[4], uint32_t a) {
    asm volatile("ldmatrix.sync.aligned.m8n8.x4.trans.shared.b16 {%0,%1,%2,%3}, [%4];"
                 : "=r"(r[0]), "=r"(r[1]), "=r"(r[2]), "=r"(r[3]) : "r"(a));
}
__device__ __forceinline__ void mma16816(float d[4], const unsigned a[4], const unsigned b[2]) {
    asm volatile("mma.sync.aligned.m16n8k16.row.col.f32.bf16.bf16.f32 "
                 "{%0,%1,%2,%3}, {%4,%5,%6,%7}, {%8,%9}, {%0,%1,%2,%3};"
                 : "+f"(d[0]), "+f"(d[1]), "+f"(d[2]), "+f"(d[3])
                 : "r"(a[0]), "r"(a[1]), "r"(a[2]), "r"(a[3]), "r"(b[0]), "r"(b[1]));
}

__global__ __launch_bounds__(NT, 2)
void main_kernel(const float* __restrict__ Wo_w,
                 float* __restrict__ out) {
    extern __shared__ __align__(16) char dynS[];
    __nv_bfloat16* As   = (__nv_bfloat16*)(dynS + OFF_AS);
    __nv_bfloat16* Bs   = (__nv_bfloat16*)(dynS + OFF_BS);
    float*         woS  = (float*)        (dynS + OFF_WO);
    float*         aiS  = (float*)        (dynS + OFF_AI);
    __nv_bfloat16* hibS = (__nv_bfloat16*)(dynS + OFF_HIB);
    float*         red  = (float*)        (dynS + OFF_RED);

    const int jh = blockIdx.x;          // 0..3 : jt*2 + ht
    const int jt = jh >> 1, ht = jh & 1;
    const int i  = blockIdx.y, b = blockIdx.z;
    const int jbase = jt * 128, hbase = ht * 128;
    const int tid  = threadIdx.x;
    const int lane = tid & 31, warp = tid >> 5;
    const int wm = warp >> 2, wn = warp & 3;   // warp tile: m = wm*32, n = wn*32

    // ---- preload small tensors ----
    if (tid < 256) hibS[tid] = g_hsb[(b * L_ + i) * H_ + tid];
    if (tid < 128) aiS[tid]  = g_A[(b * L_ + i) * H_ + hbase + tid];
    for (int t = tid; t < 128 * C_; t += NT)
        woS[(t / C_) * 8 + (t % C_)] = Wo_w[(hbase + t / C_) * C_ + (t % C_)];
    __syncthreads();

    float acc[2][4][4];
    #pragma unroll
    for (int mt = 0; mt < 2; mt++)
        #pragma unroll
        for (int nt = 0; nt < 4; nt++)
            #pragma unroll
            for (int q = 0; q < 4; q++) acc[mt][nt][q] = 0.f;

    const uint32_t AsA = (uint32_t)__cvta_generic_to_shared(As);
    const uint32_t BsA = (uint32_t)__cvta_generic_to_shared(Bs);
    const int g  = lane >> 3, r8 = lane & 7;
    const int arow  = ((g & 1) << 3) + r8;
    const int acolg = (g >> 1) << 3;
    const int browg = ((g & 1) << 3) + r8;
    const int bcol  = (g >> 1) << 3;

    // As staging map: 4 threads per j-row, 16-element k segments
    const int sj = tid >> 2;
    const int sk = (tid & 3) * 16;
    const __nv_bfloat16* hsrow = g_hsb + (b * L_ + jbase + sj) * H_;
    // Bs staging map: half-warps per k-row, 8-element h segments
    const int ln = lane & 15;
    const int krh = (lane >> 4);

    for (int kk = 0; kk < H_; kk += BK) {
        // ---- stage As[j][k'] = hsb[j, kk+k'] ----
        *(uint4*)&As[sj * SAs + sk]     = *(const uint4*)&hsrow[kk + sk];
        *(uint4*)&As[sj * SAs + sk + 8] = *(const uint4*)&hsrow[kk + sk + 8];
        // ---- stage Bs[k'][h] = hi[kk+k']*Wm[kk+k', hbase+h] + Wb[...] ----
        #pragma unroll
        for (int pass = 0; pass < 2; pass++) {
            int kr = pass * 32 + warp * 2 + krh;
            __nv_bfloat162 h2 = __bfloat162bfloat162(hibS[kk + kr]);
            const __nv_bfloat162* wmp =
                (const __nv_bfloat162*)&g_Wm[(kk + kr) * H_ + hbase + ln * 8];
            const __nv_bfloat162* wbp =
                (const __nv_bfloat162*)&g_Wb[(kk + kr) * H_ + hbase + ln * 8];
            __nv_bfloat162 t4[4];
            #pragma unroll
            for (int q = 0; q < 4; q++)
                t4[q] = __hfma2(h2, wmp[q], wbp[q]);
            *(uint4*)&Bs[kr * SBs + ln * 8] = *(uint4*)t4;
        }
        __syncthreads();

        // ---- MMA over this k-tile ----
        #pragma unroll
        for (int ks = 0; ks < BK; ks += 16) {
            unsigned af[2][4], bfr[4][2];
            #pragma unroll
            for (int mt = 0; mt < 2; mt++)
                ldsm4(af[mt], AsA + (((wm * 32 + mt * 16 + arow) * SAs + ks + acolg) << 1));
            #pragma unroll
            for (int p = 0; p < 2; p++) {
                unsigned q[4];
                ldsm4t(q, BsA + (((ks + browg) * SBs + wn * 32 + p * 16 + bcol) << 1));
                bfr[2 * p][0] = q[0]; bfr[2 * p][1] = q[1];
                bfr[2 * p + 1][0] = q[2]; bfr[2 * p + 1][1] = q[3];
            }
            #pragma unroll
            for (int mt = 0; mt < 2; mt++)
                #pragma unroll
                for (int nt = 0; nt < 4; nt++)
                    mma16816(acc[mt][nt], af[mt], bfr[nt]);
        }
        __syncthreads();
    }

    // ---- fused epilogue (h indices local to this half) ----
    float ps[4][C_];
    #pragma unroll
    for (int ri = 0; ri < 4; ri++)
        #pragma unroll
        for (int cc = 0; cc < C_; cc++) ps[ri][cc] = 0.f;

    const int rb = lane >> 2, qc = (lane & 3) * 2;
    #pragma unroll
    for (int nt = 0; nt < 4; nt++) {
        int c = wn * 32 + nt * 8 + qc;
        float ai0 = aiS[c], ai1 = aiS[c + 1];
        float4 wv0 = *(const float4*)&woS[c * 8];
        float  w04 = woS[c * 8 + 4];
        float4 wv1 = *(const float4*)&woS[(c + 1) * 8];
        float  w14 = woS[(c + 1) * 8 + 4];
        float w0[5] = {wv0.x, wv0.y, wv0.z, wv0.w, w04};
        float w1[5] = {wv1.x, wv1.y, wv1.z, wv1.w, w14};
        #pragma unroll
        for (int mt = 0; mt < 2; mt++) {
            int r0 = wm * 32 + mt * 16 + rb;
            int r1 = r0 + 8;
            int j0 = jbase + r0, j1 = jbase + r1;
            int d0 = min(max(j0 - i, -127), 127) + 127;
            int d1 = min(max(j1 - i, -127), 127) + 127;
            float2 R0 = *(const float2*)&g_Rt[d0 * H_ + hbase + c];
            float2 R1 = *(const float2*)&g_Rt[d1 * H_ + hbase + c];
            const float* a4 = acc[mt][nt];
            float t00 = tanha(a4[0] + ai0 + R0.x);
            float t01 = tanha(a4[1] + ai1 + R0.y);
            float t10 = tanha(a4[2] + ai0 + R1.x);
            float t11 = tanha(a4[3] + ai1 + R1.y);
            #pragma unroll
            for (int cc = 0; cc < C_; cc++) {
                ps[2 * mt][cc]     = fmaf(t00, w0[cc], fmaf(t01, w1[cc], ps[2 * mt][cc]));
                ps[2 * mt + 1][cc] = fmaf(t10, w0[cc], fmaf(t11, w1[cc], ps[2 * mt + 1][cc]));
            }
        }
    }

    // quad-reduce, then per-wn disjoint red slices (no smem atomics)
    #pragma unroll
    for (int ri = 0; ri < 4; ri++) {
        int row = wm * 32 + (ri >> 1) * 16 + (ri & 1) * 8 + rb;
        #pragma unroll
        for (int cc = 0; cc < C_; cc++) {
            float v = ps[ri][cc];
            v += __shfl_xor_sync(0xffffffffu, v, 1);
            v += __shfl_xor_sync(0xffffffffu, v, 2);
            if ((lane & 3) == 0) red[(wn * 128 + row) * C_ + cc] = v;
        }
    }
    __syncthreads();

    // final 4-slice sum + global atomic into pre-initialized out
    if (tid < 128) {
        const int j = jbase + tid;
        float* op = &out[((b * C_ + 0) * L_ + i) * L_ + j];
        #pragma unroll
        for (int cc = 0; cc < C_; cc++) {
            float v = red[tid * C_ + cc] + red[(128 + tid) * C_ + cc]
                    + red[(256 + tid) * C_ + cc] + red[(384 + tid) * C_ + cc];
            atomicAdd(op + cc * L_ * L_, v);
        }
    }
}

// ---------------------------------------------------------------------------
extern "C" void kernel_launch(void* const* d_in, const int* in_sizes, int n_in,
                              void* d_out, int out_size) {
    const float* hs   = (const float*)d_in[0];
    const int*   mask = (const int*)  d_in[1];
    const float* Wh_w = (const float*)d_in[2];
    const float* Wh_b = (const float*)d_in[3];
    const float* Wo_w = (const float*)d_in[4];
    const float* Wo_b = (const float*)d_in[5];
    float* out = (float*)d_out;

    cudaFuncSetAttribute(main_kernel,
                         cudaFuncAttributeMaxDynamicSharedMemorySize, SMEM_TOTAL);

    int prep_elems = B_ * L_ * H_ + H_ * H_ + VOCAB * H_;
    prep_kernel<<<(prep_elems + 255) / 256, 256>>>(hs, Wh_w, Wh_b);
    dim3 rg(51, 4);
    relterm_kernel<<<rg, H_>>>(Wh_w);
    a_kernel<<<(B_ * L_) / 16, H_>>>(hs, Wh_w);
    outinit_kernel<<<(B_ * C_ * L_ * L_ + 255) / 256, 256>>>(mask, Wo_b, out);
    dim3 grid(4, L_, B_);
    main_kernel<<<grid, NT, SMEM_TOTAL>>>(Wo_w, out);
}